// round 3
// baseline (speedup 1.0000x reference)
#include <cuda_runtime.h>
#include <math.h>

// Problem dims
#define BB 64
#define TT 2048
#define II 512
#define HH 512
#define GG 2048            // 4*H
#define NC 128             // persistent CTAs (<= 148 SMs -> co-resident)
#define TPB 256
#define HS_STRIDE 516      // 512 + 4 pad: stride in floats; 129 float4s (odd) -> conflict-free

// ---------------- device scratch (static: no allocation APIs allowed) ----------------
__device__ float    g_gatesx[(size_t)BB * TT * GG];   // 1 GB: gates_x[b][t][g]
__device__ float    g_hbuf[2][BB * HH];               // double-buffered hidden state
__device__ unsigned g_bar;                            // grid barrier counter

// ---------------- init: reset barrier + h0 (runs every launch) ----------------
__global__ void init_k() {
    int i = blockIdx.x * blockDim.x + threadIdx.x;
    if (i == 0) g_bar = 0u;
    for (int k = i; k < BB * HH; k += gridDim.x * blockDim.x) g_hbuf[0][k] = 0.f;
}

// ---------------- phase 1: gates_x = x @ Wx^T + bx + bh ----------------
// M = B*T = 131072 (row m = b*T + t, matches x layout), N = 2048, K = 512.
// 128x128 tile, BK=16, 256 threads, 8x8 per thread. FFMA-bound.
__global__ __launch_bounds__(256) void gemm_x_kernel(
    const float* __restrict__ x, const float* __restrict__ Wx,
    const float* __restrict__ bx, const float* __restrict__ bh)
{
    __shared__ float As[16][128];
    __shared__ float Bs[16][128];
    const int m0 = blockIdx.x * 128;
    const int n0 = blockIdx.y * 128;
    const int tid = threadIdx.x;
    const int tx = tid & 15, ty = tid >> 4;

    float acc[8][8];
#pragma unroll
    for (int i = 0; i < 8; i++)
#pragma unroll
        for (int j = 0; j < 8; j++) acc[i][j] = 0.f;

    for (int k0 = 0; k0 < II; k0 += 16) {
#pragma unroll
        for (int r = 0; r < 2; r++) {
            int v = tid + r * 256;          // 0..511
            int row = v >> 2, c4 = v & 3;   // 128 rows x 4 float4
            float4 a = *(const float4*)(x + (size_t)(m0 + row) * II + k0 + c4 * 4);
            As[c4 * 4 + 0][row] = a.x; As[c4 * 4 + 1][row] = a.y;
            As[c4 * 4 + 2][row] = a.z; As[c4 * 4 + 3][row] = a.w;
            float4 b = *(const float4*)(Wx + (size_t)(n0 + row) * II + k0 + c4 * 4);
            Bs[c4 * 4 + 0][row] = b.x; Bs[c4 * 4 + 1][row] = b.y;
            Bs[c4 * 4 + 2][row] = b.z; Bs[c4 * 4 + 3][row] = b.w;
        }
        __syncthreads();
#pragma unroll
        for (int kk = 0; kk < 16; kk++) {
            float4 a0 = *(const float4*)&As[kk][ty * 8];
            float4 a1 = *(const float4*)&As[kk][ty * 8 + 4];
            float4 b0 = *(const float4*)&Bs[kk][tx * 8];
            float4 b1 = *(const float4*)&Bs[kk][tx * 8 + 4];
            float a[8] = {a0.x, a0.y, a0.z, a0.w, a1.x, a1.y, a1.z, a1.w};
            float b[8] = {b0.x, b0.y, b0.z, b0.w, b1.x, b1.y, b1.z, b1.w};
#pragma unroll
            for (int i = 0; i < 8; i++)
#pragma unroll
                for (int j = 0; j < 8; j++) acc[i][j] += a[i] * b[j];
        }
        __syncthreads();
    }

    const int n = n0 + tx * 8;
    float bb[8];
#pragma unroll
    for (int j = 0; j < 8; j++) bb[j] = bx[n + j] + bh[n + j];
#pragma unroll
    for (int i = 0; i < 8; i++) {
        size_t m = (size_t)(m0 + ty * 8 + i);
        float* op = g_gatesx + m * GG + n;
        float4 v0 = make_float4(acc[i][0] + bb[0], acc[i][1] + bb[1],
                                acc[i][2] + bb[2], acc[i][3] + bb[3]);
        float4 v1 = make_float4(acc[i][4] + bb[4], acc[i][5] + bb[5],
                                acc[i][6] + bb[6], acc[i][7] + bb[7]);
        *(float4*)op = v0;
        *(float4*)(op + 4) = v1;
    }
}

// ---------------- phase 2: persistent recurrence ----------------
// 128 CTAs x 256 threads. CTA owns j in [j0, j0+4). Thread (b, jq) computes
// gates i,f,g,o for (b, j0+jq); c,h stay in registers across all 2048 steps.
// Wh slice (16 rows x 512) resident in SMEM; reads are warp-uniform broadcasts.
// h staged per step from global (L2) into padded SMEM. Double-buffered h +
// one fenced grid barrier per step.
extern __shared__ float smem[];
__global__ __launch_bounds__(256) void lstm_rec_kernel(
    const float* __restrict__ Wh, float* __restrict__ out)
{
    float* Whs = smem;                       // 16*512 floats
    float* hs  = smem + 16 * II;             // 64 rows, stride HS_STRIDE
    float* gxs = hs + BB * HS_STRIDE;        // 64*16 floats

    const int tid = threadIdx.x;
    const int j0  = blockIdx.x * 4;
    const int b   = tid & 63;
    const int jq  = tid >> 6;
    const int j   = j0 + jq;

    // Load Wh slice: row r = jq*4 + gate  <-  Wh[gate*H + j0 + jq][:]
    for (int idx = tid; idx < 16 * II; idx += TPB) {
        int r = idx >> 9, k = idx & 511;
        int gate = r & 3, q = r >> 2;
        Whs[idx] = Wh[(size_t)(gate * HH + j0 + q) * HH + k];
    }

    const float4* wi = (const float4*)(Whs + (jq * 4 + 0) * II);
    const float4* wf = (const float4*)(Whs + (jq * 4 + 1) * II);
    const float4* wg = (const float4*)(Whs + (jq * 4 + 2) * II);
    const float4* wo = (const float4*)(Whs + (jq * 4 + 3) * II);
    const float4* hrow = (const float4*)(hs + b * HS_STRIDE);

    const int sb = tid >> 2;    // staging: b index for gates_x tile
    const int sg = tid & 3;     // staging: gate index

    float c = 0.f, h = 0.f;
    unsigned target = NC;

    for (int t = 0; t < TT; t++) {
        // ---- stage h (read buffer t&1; bypass L1 — other SMs wrote it) ----
        const float4* gh4 = (const float4*)g_hbuf[t & 1];
        for (int idx = tid; idx < (BB * II) / 4; idx += TPB) {
            int b_ = idx >> 7, k4 = idx & 127;
            float4 v = __ldcg(gh4 + idx);
            *(float4*)(hs + b_ * HS_STRIDE + k4 * 4) = v;
        }
        // ---- stage gates_x[b][t][gate*512 + j0 .. +3] (one float4/thread) ----
        {
            float4 v = *(const float4*)(g_gatesx +
                          ((size_t)sb * TT + t) * GG + (size_t)sg * HH + j0);
            ((float4*)gxs)[tid] = v;
        }
        __syncthreads();

        // ---- 4 dot products of length 512 (FFMA-bound core) ----
        float ai = 0.f, af = 0.f, ag = 0.f, ao = 0.f;
#pragma unroll 4
        for (int k4 = 0; k4 < 128; k4++) {
            float4 hv = hrow[k4];
            float4 a = wi[k4];  ai += hv.x * a.x + hv.y * a.y + hv.z * a.z + hv.w * a.w;
            float4 f4 = wf[k4]; af += hv.x * f4.x + hv.y * f4.y + hv.z * f4.z + hv.w * f4.w;
            float4 g4 = wg[k4]; ag += hv.x * g4.x + hv.y * g4.y + hv.z * g4.z + hv.w * g4.w;
            float4 o4 = wo[k4]; ao += hv.x * o4.x + hv.y * o4.y + hv.z * o4.z + hv.w * o4.w;
        }

        // ---- pointwise LSTM cell ----
        float xi = ai + gxs[b * 16 + 0  + jq];
        float xf = af + gxs[b * 16 + 4  + jq];
        float xg = ag + gxs[b * 16 + 8  + jq];
        float xo = ao + gxs[b * 16 + 12 + jq];
        float si = 1.f / (1.f + expf(-xi));
        float sf = 1.f / (1.f + expf(-xf));
        float tg = tanhf(xg);
        float so = 1.f / (1.f + expf(-xo));
        c = sf * c + si * tg;
        h = so * tanhf(c);

        out[((size_t)b * TT + t) * HH + j] = h;
        g_hbuf[(t & 1) ^ 1][b * HH + j] = h;   // write the other buffer

        // ---- grid barrier (release h writes, acquire for next staging) ----
        __threadfence();
        __syncthreads();
        if (tid == 0) {
            atomicAdd(&g_bar, 1u);
            while (*(volatile unsigned*)&g_bar < target) { }
            __threadfence();
        }
        __syncthreads();
        target += NC;
    }

    // finals: h_n then c_n appended after output
    out[(size_t)BB * TT * HH + (size_t)b * HH + j] = h;
    out[(size_t)BB * TT * HH + BB * HH + (size_t)b * HH + j] = c;
}

// ---------------- launch ----------------
extern "C" void kernel_launch(void* const* d_in, const int* in_sizes, int n_in,
                              void* d_out, int out_size)
{
    const float* x  = (const float*)d_in[0];
    const float* Wx = (const float*)d_in[1];
    const float* bx = (const float*)d_in[2];
    const float* Wh = (const float*)d_in[3];
    const float* bh = (const float*)d_in[4];
    float* out = (float*)d_out;

    init_k<<<32, 256>>>();

    dim3 grid_g(131072 / 128, GG / 128);   // 1024 x 16
    gemm_x_kernel<<<grid_g, 256>>>(x, Wx, bx, bh);

    const int smem_bytes = (16 * II + BB * HS_STRIDE + BB * 16) * (int)sizeof(float); // 168960
    cudaFuncSetAttribute(lstm_rec_kernel,
                         cudaFuncAttributeMaxDynamicSharedMemorySize, smem_bytes);
    lstm_rec_kernel<<<NC, TPB, smem_bytes>>>(Wh, out);
    (void)in_sizes; (void)n_in; (void)out_size;
}